// round 5
// baseline (speedup 1.0000x reference)
#include <cuda_runtime.h>
#include <math.h>

#define Bb 2
#define Tt 1024
#define Cc 2048
#define Hh 32
#define Nn 64
#define Mm (Bb*Tt)

// ---------------- device scratch ----------------
__device__ float g_xx[Mm*Cc];
__device__ float g_r [Mm*Cc];
__device__ float g_k [Mm*Cc];
__device__ float g_v [Mm*Cc];
__device__ float g_w [Mm*Cc];   // decay exp(logdecay)
__device__ float g_a [Mm*Cc];   // a, then overwritten with b = kk*a
__device__ float g_kk[Mm*Cc];
__device__ float g_g [Mm*Cc];
__device__ float g_o [Mm*Cc];
__device__ float g_xo[Mm*Cc];
__device__ float g_t1w[Mm*64];
__device__ float g_t1a[Mm*64];
__device__ float g_t1v[Mm*32];
__device__ float g_t1g[Mm*128];

__device__ __forceinline__ float sigm(float x) { return 1.0f / (1.0f + expf(-x)); }

// ---------------- 1) token shift: xx = prev - h ----------------
__global__ void k_prep(const float* __restrict__ h, const float* __restrict__ shift) {
    int idx = blockIdx.x * 256 + threadIdx.x;
    int c = idx & (Cc - 1);
    int m = idx >> 11;
    int t = m & (Tt - 1);
    int b = m >> 10;
    float prev = (t == 0) ? shift[b * Cc + c] : h[idx - Cc];
    g_xx[idx] = prev - h[idx];
}

// ---------------- 2) big GEMM: out[m,n] = sum_k A'[m,k] * W[n,k] ----------------
// SEL 0/1/2: A' = h + xx*mix, out = g_r/g_k/g_v.  SEL 3: A' = g_xo, out = Cout.
template<int SEL>
__global__ __launch_bounds__(256) void k_gemm(
    const float* __restrict__ A, const float* __restrict__ mixv,
    const float* __restrict__ W, float* __restrict__ Cout)
{
    constexpr bool HASMIX = (SEL < 3);
    __shared__ float As[2][8][128];
    __shared__ float Bs[2][8][128];

    const int tid = threadIdx.x;
    const int m0 = blockIdx.y * 128;
    const int n0 = blockIdx.x * 128;
    const int lr = tid >> 1;
    const int lc = (tid & 1) << 2;

    const float* Abase = (SEL == 3) ? (const float*)g_xo : A;
    const float* Ap = Abase + (m0 + lr) * Cc + lc;
    const float* Xp = g_xx  + (m0 + lr) * Cc + lc;
    const float* Bp = W     + (n0 + lr) * Cc + lc;

    float4 aR, bR;
    aR = *(const float4*)(Ap);
    if (HASMIX) {
        float4 x4 = *(const float4*)(Xp);
        float4 m4 = *(const float4*)(mixv + lc);
        aR.x = fmaf(x4.x, m4.x, aR.x); aR.y = fmaf(x4.y, m4.y, aR.y);
        aR.z = fmaf(x4.z, m4.z, aR.z); aR.w = fmaf(x4.w, m4.w, aR.w);
    }
    bR = *(const float4*)(Bp);
    As[0][lc+0][lr] = aR.x; As[0][lc+1][lr] = aR.y; As[0][lc+2][lr] = aR.z; As[0][lc+3][lr] = aR.w;
    Bs[0][lc+0][lr] = bR.x; Bs[0][lc+1][lr] = bR.y; Bs[0][lc+2][lr] = bR.z; Bs[0][lc+3][lr] = bR.w;
    __syncthreads();

    float acc[8][8];
    #pragma unroll
    for (int i = 0; i < 8; ++i)
        #pragma unroll
        for (int j = 0; j < 8; ++j) acc[i][j] = 0.0f;

    const int tx = tid & 15, ty = tid >> 4;

    #pragma unroll 1
    for (int kt = 0; kt < 256; ++kt) {
        const int cur = kt & 1;
        if (kt < 255) {
            const int k = (kt + 1) * 8;
            aR = *(const float4*)(Ap + k);
            if (HASMIX) {
                float4 x4 = *(const float4*)(Xp + k);
                float4 m4 = *(const float4*)(mixv + k + lc);
                aR.x = fmaf(x4.x, m4.x, aR.x); aR.y = fmaf(x4.y, m4.y, aR.y);
                aR.z = fmaf(x4.z, m4.z, aR.z); aR.w = fmaf(x4.w, m4.w, aR.w);
            }
            bR = *(const float4*)(Bp + k);
        }
        #pragma unroll
        for (int kk = 0; kk < 8; ++kk) {
            float4 a0 = *(const float4*)&As[cur][kk][ty * 8];
            float4 a1 = *(const float4*)&As[cur][kk][ty * 8 + 4];
            float4 b0 = *(const float4*)&Bs[cur][kk][tx * 8];
            float4 b1 = *(const float4*)&Bs[cur][kk][tx * 8 + 4];
            float av[8] = {a0.x,a0.y,a0.z,a0.w,a1.x,a1.y,a1.z,a1.w};
            float bv[8] = {b0.x,b0.y,b0.z,b0.w,b1.x,b1.y,b1.z,b1.w};
            #pragma unroll
            for (int i = 0; i < 8; ++i)
                #pragma unroll
                for (int j = 0; j < 8; ++j)
                    acc[i][j] = fmaf(av[i], bv[j], acc[i][j]);
        }
        if (kt < 255) {
            const int nb = cur ^ 1;
            As[nb][lc+0][lr] = aR.x; As[nb][lc+1][lr] = aR.y; As[nb][lc+2][lr] = aR.z; As[nb][lc+3][lr] = aR.w;
            Bs[nb][lc+0][lr] = bR.x; Bs[nb][lc+1][lr] = bR.y; Bs[nb][lc+2][lr] = bR.z; Bs[nb][lc+3][lr] = bR.w;
            __syncthreads();
        }
    }

    float* outp = (SEL == 0) ? g_r : (SEL == 1) ? g_k : (SEL == 2) ? g_v : Cout;
    #pragma unroll
    for (int i = 0; i < 8; ++i) {
        float* cp = outp + (m0 + ty * 8 + i) * Cc + n0 + tx * 8;
        *(float4*)cp       = make_float4(acc[i][0], acc[i][1], acc[i][2], acc[i][3]);
        *(float4*)(cp + 4) = make_float4(acc[i][4], acc[i][5], acc[i][6], acc[i][7]);
    }
}

// ---------------- 3) small GEMM stage 1: t1 = act((h + xx*mix) @ W1) ----------------
__global__ __launch_bounds__(256) void k_small1(
    const float* __restrict__ h,
    const float* __restrict__ xw, const float* __restrict__ xa,
    const float* __restrict__ xv, const float* __restrict__ xg,
    const float* __restrict__ w1, const float* __restrict__ a1,
    const float* __restrict__ v1, const float* __restrict__ g1)
{
    const int chunk = blockIdx.y;
    const float* mixv; const float* W; float* out; int D; int cbase; int act;
    if (chunk < 2)      { mixv = xw; W = w1; out = g_t1w; D = 64;  cbase = chunk * 32;       act = 1; }
    else if (chunk < 4) { mixv = xa; W = a1; out = g_t1a; D = 64;  cbase = (chunk - 2) * 32; act = 0; }
    else if (chunk < 5) { mixv = xv; W = v1; out = g_t1v; D = 32;  cbase = 0;                act = 0; }
    else                { mixv = xg; W = g1; out = g_t1g; D = 128; cbase = (chunk - 5) * 32; act = 2; }

    const int tid = threadIdx.x;
    const int tc = tid & 7;
    const int tr = tid >> 3;
    const int c0 = cbase + tc * 4;
    const int m0 = blockIdx.x * 128 + tr * 4;
    const float* h0 = h    + m0 * Cc;
    const float* x0 = g_xx + m0 * Cc;

    float acc[4][4];
    #pragma unroll
    for (int r = 0; r < 4; ++r)
        #pragma unroll
        for (int j = 0; j < 4; ++j) acc[r][j] = 0.0f;

    for (int k = 0; k < Cc; k += 4) {
        float4 m4  = *(const float4*)(mixv + k);
        float4 wr0 = *(const float4*)(W + (k + 0) * D + c0);
        float4 wr1 = *(const float4*)(W + (k + 1) * D + c0);
        float4 wr2 = *(const float4*)(W + (k + 2) * D + c0);
        float4 wr3 = *(const float4*)(W + (k + 3) * D + c0);
        #pragma unroll
        for (int r = 0; r < 4; ++r) {
            float4 h4 = *(const float4*)(h0 + r * Cc + k);
            float4 x4 = *(const float4*)(x0 + r * Cc + k);
            float A0 = fmaf(x4.x, m4.x, h4.x);
            float A1 = fmaf(x4.y, m4.y, h4.y);
            float A2 = fmaf(x4.z, m4.z, h4.z);
            float A3 = fmaf(x4.w, m4.w, h4.w);
            acc[r][0] = fmaf(A0, wr0.x, fmaf(A1, wr1.x, fmaf(A2, wr2.x, fmaf(A3, wr3.x, acc[r][0]))));
            acc[r][1] = fmaf(A0, wr0.y, fmaf(A1, wr1.y, fmaf(A2, wr2.y, fmaf(A3, wr3.y, acc[r][1]))));
            acc[r][2] = fmaf(A0, wr0.z, fmaf(A1, wr1.z, fmaf(A2, wr2.z, fmaf(A3, wr3.z, acc[r][2]))));
            acc[r][3] = fmaf(A0, wr0.w, fmaf(A1, wr1.w, fmaf(A2, wr2.w, fmaf(A3, wr3.w, acc[r][3]))));
        }
    }
    #pragma unroll
    for (int r = 0; r < 4; ++r)
        #pragma unroll
        for (int j = 0; j < 4; ++j) {
            float v = acc[r][j];
            if (act == 1) v = tanhf(v);
            else if (act == 2) v = sigm(v);
            out[(m0 + r) * D + c0 + j] = v;
        }
}

// ---------------- 4) small GEMM stage 2 with fused epilogues ----------------
__global__ __launch_bounds__(256) void k_small2(
    const float* __restrict__ w0b, const float* __restrict__ a0b,
    const float* __restrict__ v0b, const float* __restrict__ vfirst,
    const float* __restrict__ w2, const float* __restrict__ a2,
    const float* __restrict__ v2, const float* __restrict__ g2)
{
    const int p = blockIdx.y;
    const float* t1; const float* W2; const float* bias; float* out; int D;
    if (p == 0)      { t1 = g_t1w; W2 = w2; bias = w0b; out = g_w; D = 64; }
    else if (p == 1) { t1 = g_t1a; W2 = a2; bias = a0b; out = g_a; D = 64; }
    else if (p == 2) { t1 = g_t1v; W2 = v2; bias = v0b; out = g_v; D = 32; }
    else             { t1 = g_t1g; W2 = g2; bias = 0;   out = g_g; D = 128; }

    __shared__ float ts[8][128];
    const int tid = threadIdx.x;
    const int m0 = blockIdx.x * 8;
    for (int i = tid; i < 8 * D; i += 256)
        ts[i / D][i % D] = t1[(m0 + i / D) * D + (i % D)];
    __syncthreads();

    const int c0 = tid * 4;
    float4 acc0[8], acc1[8];
    #pragma unroll
    for (int r = 0; r < 8; ++r) { acc0[r] = make_float4(0,0,0,0); acc1[r] = make_float4(0,0,0,0); }

    for (int d = 0; d < D; ++d) {
        float4 wA = *(const float4*)(W2 + d * Cc + c0);
        float4 wB = *(const float4*)(W2 + d * Cc + c0 + 1024);
        #pragma unroll
        for (int r = 0; r < 8; ++r) {
            float t = ts[r][d];
            acc0[r].x = fmaf(t, wA.x, acc0[r].x); acc0[r].y = fmaf(t, wA.y, acc0[r].y);
            acc0[r].z = fmaf(t, wA.z, acc0[r].z); acc0[r].w = fmaf(t, wA.w, acc0[r].w);
            acc1[r].x = fmaf(t, wB.x, acc1[r].x); acc1[r].y = fmaf(t, wB.y, acc1[r].y);
            acc1[r].z = fmaf(t, wB.z, acc1[r].z); acc1[r].w = fmaf(t, wB.w, acc1[r].w);
        }
    }

    #pragma unroll
    for (int r = 0; r < 8; ++r) {
        const int row = m0 + r;
        #pragma unroll
        for (int half = 0; half < 2; ++half) {
            float4 acc = half ? acc1[r] : acc0[r];
            int cb = c0 + half * 1024;
            float vals[4] = {acc.x, acc.y, acc.z, acc.w};
            #pragma unroll
            for (int j = 0; j < 4; ++j) {
                int c = cb + j;
                int idx = row * Cc + c;
                float y = vals[j];
                if (p == 0)      out[idx] = 0.60653065971263342f * sigm(bias[c] + y);
                else if (p == 1) out[idx] = sigm(bias[c] + y);
                else if (p == 2) {
                    float s = sigm(bias[c] + y);
                    float vold = out[idx];
                    out[idx] = fmaf(vfirst[idx] - vold, s, vold);
                } else out[idx] = y;
            }
        }
    }
}

// ---------------- 5) per-head: kk normalize, k lerp, b = kk*a ----------------
__global__ void k_kfinal(const float* __restrict__ k_k, const float* __restrict__ k_a) {
    const int gw = blockIdx.x * 8 + (threadIdx.x >> 5);
    const int lane = threadIdx.x & 31;
    const int m = gw >> 5, hh = gw & 31;
    const int cb = hh * 64;
    const int i0 = m * Cc + cb + lane, i1 = i0 + 32;

    float k0 = g_k[i0], k1 = g_k[i1];
    float kk0 = k0 * k_k[cb + lane], kk1 = k1 * k_k[cb + lane + 32];
    float ss = kk0 * kk0 + kk1 * kk1;
    #pragma unroll
    for (int o = 16; o; o >>= 1) ss += __shfl_xor_sync(0xffffffffu, ss, o);
    float inv = 1.0f / fmaxf(sqrtf(ss), 1e-12f);
    kk0 *= inv; kk1 *= inv;
    g_kk[i0] = kk0; g_kk[i1] = kk1;

    float a0v = g_a[i0], a1v = g_a[i1];
    float ka0 = k_a[cb + lane], ka1 = k_a[cb + lane + 32];
    g_k[i0] = k0 + ka0 * (k0 * a0v - k0);
    g_k[i1] = k1 + ka1 * (k1 * a1v - k1);
    g_a[i0] = kk0 * a0v;
    g_a[i1] = kk1 * a1v;
}

// ---------------- 6) WKV7 recurrence ----------------
__device__ __forceinline__ float red16(float x) {
    x += __shfl_xor_sync(0xffffffffu, x, 1);
    x += __shfl_xor_sync(0xffffffffu, x, 2);
    x += __shfl_xor_sync(0xffffffffu, x, 4);
    x += __shfl_xor_sync(0xffffffffu, x, 8);
    return x;
}

__global__ __launch_bounds__(256) void k_wkv(const float* __restrict__ s0) {
    const int tid = threadIdx.x;
    const int vloc = tid >> 4, kg = tid & 15, k0 = kg * 4;
    const int blk = blockIdx.x;
    const int bh = blk >> 2;
    const int v = (blk & 3) * 16 + vloc;
    const int b = bh >> 5, hh = bh & 31;

    float4 S = *(const float4*)(s0 + (bh * 64 + v) * 64 + k0);
    int off = (b * Tt) * Cc + hh * 64;

    const float* pr  = g_r  + k0;
    const float* pk  = g_k  + k0;
    const float* pd  = g_w  + k0;
    const float* pkk = g_kk + k0;
    const float* pb  = g_a  + k0;

    float4 r4  = *(const float4*)(pr  + off);
    float4 k4  = *(const float4*)(pk  + off);
    float4 d4  = *(const float4*)(pd  + off);
    float4 kk4 = *(const float4*)(pkk + off);
    float4 b4  = *(const float4*)(pb  + off);
    float  vt  = g_v[off + v];

    #pragma unroll 1
    for (int t = 0; t < Tt; ++t) {
        float4 rc = r4, kc = k4, dc = d4, kkc = kk4, bc = b4;
        float vc = vt;
        int offn = off + Cc;
        if (t < Tt - 1) {
            r4  = *(const float4*)(pr  + offn);
            k4  = *(const float4*)(pk  + offn);
            d4  = *(const float4*)(pd  + offn);
            kk4 = *(const float4*)(pkk + offn);
            b4  = *(const float4*)(pb  + offn);
            vt  = g_v[offn + v];
        }
        float sap = S.x*kkc.x + S.y*kkc.y + S.z*kkc.z + S.w*kkc.w;
        float sa = -red16(sap);
        S.x = fmaf(S.x, dc.x, fmaf(sa, bc.x, vc * kc.x));
        S.y = fmaf(S.y, dc.y, fmaf(sa, bc.y, vc * kc.y));
        S.z = fmaf(S.z, dc.z, fmaf(sa, bc.z, vc * kc.z));
        S.w = fmaf(S.w, dc.w, fmaf(sa, bc.w, vc * kc.w));
        float op = S.x*rc.x + S.y*rc.y + S.z*rc.z + S.w*rc.w;
        op = red16(op);
        if (kg == 0) g_o[off + v] = op;
        off = offn;
    }
}

// ---------------- 7) groupnorm + bonus + gating -> g_xo ----------------
__global__ void k_gnorm(const float* __restrict__ rk,
                        const float* __restrict__ gnw, const float* __restrict__ gnb) {
    const int gw = blockIdx.x * 8 + (threadIdx.x >> 5);
    const int lane = threadIdx.x & 31;
    const int m = gw >> 5, hh = gw & 31;
    const int cb = hh * 64;
    const int i0 = m * Cc + cb + lane, i1 = i0 + 32;

    float o0 = g_o[i0], o1 = g_o[i1];
    float s = o0 + o1;
    #pragma unroll
    for (int o = 16; o; o >>= 1) s += __shfl_xor_sync(0xffffffffu, s, o);
    float mean = s * (1.0f / 64.0f);
    float d0 = o0 - mean, d1 = o1 - mean;
    float q = d0 * d0 + d1 * d1;
    #pragma unroll
    for (int o = 16; o; o >>= 1) q += __shfl_xor_sync(0xffffffffu, q, o);
    float inv = rsqrtf(q * (1.0f / 64.0f) + 6.4e-4f);

    float xn0 = d0 * inv * gnw[cb + lane]      + gnb[cb + lane];
    float xn1 = d1 * inv * gnw[cb + lane + 32] + gnb[cb + lane + 32];

    float p = g_r[i0] * g_k[i0] * rk[cb + lane] + g_r[i1] * g_k[i1] * rk[cb + lane + 32];
    #pragma unroll
    for (int o = 16; o; o >>= 1) p += __shfl_xor_sync(0xffffffffu, p, o);

    float x0 = xn0 + p * g_v[i0];
    float x1 = xn1 + p * g_v[i1];
    g_xo[i0] = x0 * g_g[i0];
    g_xo[i1] = x1 * g_g[i1];
}

// ---------------- launch ----------------
extern "C" void kernel_launch(void* const* d_in, const int* in_sizes, int n_in,
                              void* d_out, int out_size) {
    const float* h      = (const float*)d_in[0];
    const float* shift  = (const float*)d_in[1];
    const float* s0     = (const float*)d_in[2];
    const float* vfirst = (const float*)d_in[3];
    const float* x_r = (const float*)d_in[4];
    const float* x_w = (const float*)d_in[5];
    const float* x_k = (const float*)d_in[6];
    const float* x_v = (const float*)d_in[7];
    const float* x_a = (const float*)d_in[8];
    const float* x_g = (const float*)d_in[9];
    const float* w0 = (const float*)d_in[10];
    const float* w1 = (const float*)d_in[11];
    const float* w2 = (const float*)d_in[12];
    const float* a0 = (const float*)d_in[13];
    const float* a1 = (const float*)d_in[14];
    const float* a2 = (const float*)d_in[15];
    const float* v0 = (const float*)d_in[16];
    const float* v1 = (const float*)d_in[17];
    const float* v2 = (const float*)d_in[18];
    const float* g1 = (const float*)d_in[19];
    const float* g2 = (const float*)d_in[20];
    const float* k_k = (const float*)d_in[21];
    const float* k_a = (const float*)d_in[22];
    const float* r_k = (const float*)d_in[23];
    const float* W_r = (const float*)d_in[24];
    const float* W_k = (const float*)d_in[25];
    const float* W_v = (const float*)d_in[26];
    const float* W_o = (const float*)d_in[27];
    const float* gn_w = (const float*)d_in[28];
    const float* gn_b = (const float*)d_in[29];
    float* out = (float*)d_out;

    k_prep<<<Mm * Cc / 256, 256>>>(h, shift);
    dim3 g16(16, 16);
    k_gemm<0><<<g16, 256>>>(h, x_r, W_r, nullptr);
    k_gemm<1><<<g16, 256>>>(h, x_k, W_k, nullptr);
    k_gemm<2><<<g16, 256>>>(h, x_v, W_v, nullptr);
    k_small1<<<dim3(16, 9), 256>>>(h, x_w, x_a, x_v, x_g, w1, a1, v1, g1);
    k_small2<<<dim3(256, 4), 256>>>(w0, a0, v0, vfirst, w2, a2, v2, g2);
    k_kfinal<<<8192, 256>>>(k_k, k_a);
    k_wkv<<<256, 256>>>(s0);
    k_gnorm<<<8192, 256>>>(r_k, gn_w, gn_b);
    k_gemm<3><<<g16, 256>>>(nullptr, nullptr, W_o, out);
}

// round 13
// speedup vs baseline: 1.7420x; 1.7420x over previous
#include <cuda_runtime.h>
#include <cuda_bf16.h>
#include <math.h>
#include <stdint.h>

#define Bb 2
#define Tt 1024
#define Cc 2048
#define Hh 32
#define Nn 64
#define Mm (Bb*Tt)
#define MC (Mm*Cc)
#define CC (Cc*Cc)

// ---------------- device scratch ----------------
__device__ float g_xx[MC];
__device__ float g_r [MC];
__device__ float g_k [MC];
__device__ float g_v [MC];
__device__ float g_w [MC];   // decay exp(logdecay)
__device__ float g_a [MC];   // a, then overwritten with b = kk*a
__device__ float g_kk[MC];
__device__ float g_g [MC];
__device__ float g_o [MC];
__device__ float g_t1w[Mm*64];
__device__ float g_t1a[Mm*64];
__device__ float g_t1v[Mm*32];
__device__ float g_t1g[Mm*128];

// bf16 hi/lo split operands for tensor-core GEMMs
__device__ __nv_bfloat16 g_Whi[4][CC];   // W_r, W_k, W_v, W_o
__device__ __nv_bfloat16 g_Wlo[4][CC];
__device__ __nv_bfloat16 g_Ahi[4][MC];   // A_r, A_k, A_v, xo
__device__ __nv_bfloat16 g_Alo[4][MC];

__device__ __forceinline__ float sigm(float x) { return 1.0f / (1.0f + expf(-x)); }

__device__ __forceinline__ void split2(float a, __nv_bfloat16& hi, __nv_bfloat16& lo) {
    hi = __float2bfloat16(a);
    lo = __float2bfloat16(a - __bfloat162float(hi));
}

__device__ __forceinline__ uint32_t smem_u32(const void* p) {
    uint32_t a;
    asm("{ .reg .u64 t; cvta.to.shared.u64 t, %1; cvt.u32.u64 %0, t; }" : "=r"(a) : "l"(p));
    return a;
}

__device__ __forceinline__ void ldm_x4(uint32_t* r, uint32_t addr) {
    asm volatile("ldmatrix.sync.aligned.m8n8.x4.shared.b16 {%0,%1,%2,%3}, [%4];"
        : "=r"(r[0]), "=r"(r[1]), "=r"(r[2]), "=r"(r[3]) : "r"(addr));
}

__device__ __forceinline__ void mma_bf16(float* c, const uint32_t* a, const uint32_t* b) {
    asm volatile("mma.sync.aligned.m16n8k16.row.col.f32.bf16.bf16.f32 "
        "{%0,%1,%2,%3}, {%4,%5,%6,%7}, {%8,%9}, {%0,%1,%2,%3};"
        : "+f"(c[0]), "+f"(c[1]), "+f"(c[2]), "+f"(c[3])
        : "r"(a[0]), "r"(a[1]), "r"(a[2]), "r"(a[3]), "r"(b[0]), "r"(b[1]));
}

#define CP_ASYNC16(smem, gptr) \
    asm volatile("cp.async.cg.shared.global [%0], [%1], 16;" :: "r"(smem), "l"(gptr))
#define CP_COMMIT() asm volatile("cp.async.commit_group;" ::: "memory")
#define CP_WAIT0()  asm volatile("cp.async.wait_group 0;" ::: "memory")

// ---------------- 1) token shift: xx = prev - h ----------------
__global__ void k_prep(const float* __restrict__ h, const float* __restrict__ shift) {
    int idx = blockIdx.x * 256 + threadIdx.x;
    int c = idx & (Cc - 1);
    int m = idx >> 11;
    int t = m & (Tt - 1);
    int b = m >> 10;
    float prev = (t == 0) ? shift[b * Cc + c] : h[idx - Cc];
    g_xx[idx] = prev - h[idx];
}

// ---------------- 2a) weight split to bf16 hi/lo ----------------
__global__ void k_convW(const float* __restrict__ wr, const float* __restrict__ wk,
                        const float* __restrict__ wv, const float* __restrict__ wo) {
    const int which = blockIdx.y;
    const float* src = (which == 0) ? wr : (which == 1) ? wk : (which == 2) ? wv : wo;
    const int i = (blockIdx.x * 256 + threadIdx.x) * 4;
    float4 v = *(const float4*)(src + i);
    __align__(8) __nv_bfloat16 hi[4], lo[4];
    split2(v.x, hi[0], lo[0]); split2(v.y, hi[1], lo[1]);
    split2(v.z, hi[2], lo[2]); split2(v.w, hi[3], lo[3]);
    *(uint2*)(&g_Whi[which][i]) = *(uint2*)hi;
    *(uint2*)(&g_Wlo[which][i]) = *(uint2*)lo;
}

// ---------------- 2b) activation operands: a = h + xx*mix, split ----------------
__global__ void k_makeA(const float* __restrict__ h, const float* __restrict__ xr,
                        const float* __restrict__ xk, const float* __restrict__ xv) {
    const int sel = blockIdx.y;
    const float* mix = (sel == 0) ? xr : (sel == 1) ? xk : xv;
    const int i = (blockIdx.x * 256 + threadIdx.x) * 4;
    const int c = i & (Cc - 1);
    float4 hv = *(const float4*)(h + i);
    float4 xv4 = *(const float4*)(g_xx + i);
    float4 m4 = *(const float4*)(mix + c);
    float a0 = fmaf(xv4.x, m4.x, hv.x);
    float a1 = fmaf(xv4.y, m4.y, hv.y);
    float a2 = fmaf(xv4.z, m4.z, hv.z);
    float a3 = fmaf(xv4.w, m4.w, hv.w);
    __align__(8) __nv_bfloat16 hi[4], lo[4];
    split2(a0, hi[0], lo[0]); split2(a1, hi[1], lo[1]);
    split2(a2, hi[2], lo[2]); split2(a3, hi[3], lo[3]);
    *(uint2*)(&g_Ahi[sel][i]) = *(uint2*)hi;
    *(uint2*)(&g_Alo[sel][i]) = *(uint2*)lo;
}

// ---------------- 3) mma.sync bf16-split GEMM: Out[m,n] = sum_k A[m,k]*B[n,k] ----------------
// Block: 128x128, 256 threads (8 warps 2x4), warp tile 64x32, K-chunk 64, 2 stages.
#define TILEB 16384                  // one operand tile: 128 rows x 128 B
#define STAGEB (4*TILEB)             // Ahi, Alo, Bhi, Blo
#define SMEM_SZ (2*STAGEB)           // 131072

__device__ __forceinline__ void issue_chunk(
    const uint4* __restrict__ A0, const uint4* __restrict__ A1,
    const uint4* __restrict__ B0, const uint4* __restrict__ B1,
    uint32_t sbase, int stage, int chunk, int tid, int m0, int n0)
{
    const uint32_t sb = sbase + stage * STAGEB;
    #pragma unroll
    for (int j = 0; j < 16; ++j) {
        const int i = j * 256 + tid;
        const int tile = i >> 10;          // 0..3
        const int idx  = i & 1023;
        const int row  = idx >> 3;         // 0..127
        const int c16  = idx & 7;          // 0..7
        const uint4* src; int grow;
        if (tile == 0)      { src = A0; grow = m0 + row; }
        else if (tile == 1) { src = A1; grow = m0 + row; }
        else if (tile == 2) { src = B0; grow = n0 + row; }
        else                { src = B1; grow = n0 + row; }
        const uint4* gp = src + grow * 256 + chunk * 8 + c16;
        uint32_t soff = sb + tile * TILEB + row * 128 + ((c16 ^ (row & 7)) << 4);
        CP_ASYNC16(soff, gp);
    }
}

__global__ __launch_bounds__(256, 1) void k_gemm_tc(
    const __nv_bfloat16* __restrict__ Ahi, const __nv_bfloat16* __restrict__ Alo,
    const __nv_bfloat16* __restrict__ Bhi, const __nv_bfloat16* __restrict__ Blo,
    float* __restrict__ Out)
{
    extern __shared__ __align__(1024) char smem[];
    const uint32_t sbase = smem_u32(smem);
    const int tid = threadIdx.x;
    const int lane = tid & 31;
    const int warp = tid >> 5;
    const int wm = warp >> 2;          // 0..1  (m offset wm*64)
    const int wn = warp & 3;           // 0..3  (n offset wn*32)
    const int m0 = blockIdx.y * 128;
    const int n0 = blockIdx.x * 128;

    const uint4* A0 = (const uint4*)Ahi;
    const uint4* A1 = (const uint4*)Alo;
    const uint4* B0 = (const uint4*)Bhi;
    const uint4* B1 = (const uint4*)Blo;

    // ldmatrix per-lane addressing components
    const int mat = lane >> 3;          // 0..3
    const int mr  = lane & 7;
    const int chi = mat >> 1;           // 0: k_lo, 1: k_hi (+8 elems = +1 c16)
    // A rows for 4 m-tiles, B rows for 2 n-pairs
    int rowA[4], rowB[2];
    #pragma unroll
    for (int i = 0; i < 4; ++i) rowA[i] = wm * 64 + i * 16 + (mat & 1) * 8 + mr;
    #pragma unroll
    for (int j = 0; j < 2; ++j) rowB[j] = wn * 32 + j * 16 + (mat & 1) * 8 + mr;

    float acc[4][4][4];
    #pragma unroll
    for (int i = 0; i < 4; ++i)
        #pragma unroll
        for (int j = 0; j < 4; ++j)
            #pragma unroll
            for (int q = 0; q < 4; ++q) acc[i][j][q] = 0.0f;

    issue_chunk(A0, A1, B0, B1, sbase, 0, 0, tid, m0, n0);
    CP_COMMIT();

    #pragma unroll 1
    for (int c = 0; c < 32; ++c) {
        CP_WAIT0();
        __syncthreads();
        if (c + 1 < 32) {
            issue_chunk(A0, A1, B0, B1, sbase, (c + 1) & 1, c + 1, tid, m0, n0);
            CP_COMMIT();
        }
        const uint32_t st = sbase + (c & 1) * STAGEB;
        #pragma unroll
        for (int s = 0; s < 4; ++s) {
            const int c16 = s * 2 + chi;   // k position for this lane's matrix
            uint32_t ah[4][4], al[4][4], bh[4][2], bl[4][2];
            #pragma unroll
            for (int i = 0; i < 4; ++i) {
                uint32_t off = rowA[i] * 128 + (uint32_t)((c16 ^ (rowA[i] & 7)) << 4);
                ldm_x4(ah[i], st + off);
                ldm_x4(al[i], st + TILEB + off);
            }
            #pragma unroll
            for (int j = 0; j < 2; ++j) {
                uint32_t off = rowB[j] * 128 + (uint32_t)((c16 ^ (rowB[j] & 7)) << 4);
                uint32_t th[4], tl[4];
                ldm_x4(th, st + 2 * TILEB + off);
                ldm_x4(tl, st + 3 * TILEB + off);
                bh[2*j][0] = th[0]; bh[2*j][1] = th[2];
                bh[2*j+1][0] = th[1]; bh[2*j+1][1] = th[3];
                bl[2*j][0] = tl[0]; bl[2*j][1] = tl[2];
                bl[2*j+1][0] = tl[1]; bl[2*j+1][1] = tl[3];
            }
            #pragma unroll
            for (int i = 0; i < 4; ++i)
                #pragma unroll
                for (int j = 0; j < 4; ++j) {
                    mma_bf16(acc[i][j], ah[i], bh[j]);
                    mma_bf16(acc[i][j], ah[i], bl[j]);
                    mma_bf16(acc[i][j], al[i], bh[j]);
                }
        }
    }

    // epilogue
    const int mrow = (lane >> 2);
    const int ncol = (lane & 3) * 2;
    #pragma unroll
    for (int i = 0; i < 4; ++i) {
        #pragma unroll
        for (int j = 0; j < 4; ++j) {
            const int m = m0 + wm * 64 + i * 16 + mrow;
            const int n = n0 + wn * 32 + j * 8 + ncol;
            *(float2*)(Out + m * Cc + n)       = make_float2(acc[i][j][0], acc[i][j][1]);
            *(float2*)(Out + (m + 8) * Cc + n) = make_float2(acc[i][j][2], acc[i][j][3]);
        }
    }
}

// ---------------- 4) small GEMM stage 1: t1 = act((h + xx*mix) @ W1) ----------------
__global__ __launch_bounds__(256) void k_small1(
    const float* __restrict__ h,
    const float* __restrict__ xw, const float* __restrict__ xa,
    const float* __restrict__ xv, const float* __restrict__ xg,
    const float* __restrict__ w1, const float* __restrict__ a1,
    const float* __restrict__ v1, const float* __restrict__ g1)
{
    const int chunk = blockIdx.y;
    const float* mixv; const float* W; float* out; int D; int cbase; int act;
    if (chunk < 2)      { mixv = xw; W = w1; out = g_t1w; D = 64;  cbase = chunk * 32;       act = 1; }
    else if (chunk < 4) { mixv = xa; W = a1; out = g_t1a; D = 64;  cbase = (chunk - 2) * 32; act = 0; }
    else if (chunk < 5) { mixv = xv; W = v1; out = g_t1v; D = 32;  cbase = 0;                act = 0; }
    else                { mixv = xg; W = g1; out = g_t1g; D = 128; cbase = (chunk - 5) * 32; act = 2; }

    const int tid = threadIdx.x;
    const int tc = tid & 7;
    const int tr = tid >> 3;
    const int c0 = cbase + tc * 4;
    const int m0 = blockIdx.x * 128 + tr * 4;
    const float* h0 = h    + m0 * Cc;
    const float* x0 = g_xx + m0 * Cc;

    float acc[4][4];
    #pragma unroll
    for (int r = 0; r < 4; ++r)
        #pragma unroll
        for (int j = 0; j < 4; ++j) acc[r][j] = 0.0f;

    for (int k = 0; k < Cc; k += 4) {
        float4 m4  = *(const float4*)(mixv + k);
        float4 wr0 = *(const float4*)(W + (k + 0) * D + c0);
        float4 wr1 = *(const float4*)(W + (k + 1) * D + c0);
        float4 wr2 = *(const float4*)(W + (k + 2) * D + c0);
        float4 wr3 = *(const float4*)(W + (k + 3) * D + c0);
        #pragma unroll
        for (int r = 0; r < 4; ++r) {
            float4 h4 = *(const float4*)(h0 + r * Cc + k);
            float4 x4 = *(const float4*)(x0 + r * Cc + k);
            float A0 = fmaf(x4.x, m4.x, h4.x);
            float A1 = fmaf(x4.y, m4.y, h4.y);
            float A2 = fmaf(x4.z, m4.z, h4.z);
            float A3 = fmaf(x4.w, m4.w, h4.w);
            acc[r][0] = fmaf(A0, wr0.x, fmaf(A1, wr1.x, fmaf(A2, wr2.x, fmaf(A3, wr3.x, acc[r][0]))));
            acc[r][1] = fmaf(A0, wr0.y, fmaf(A1, wr1.y, fmaf(A2, wr2.y, fmaf(A3, wr3.y, acc[r][1]))));
            acc[r][2] = fmaf(A0, wr0.z, fmaf(A1, wr1.z, fmaf(A2, wr2.z, fmaf(A3, wr3.z, acc[r][2]))));
            acc[r][3] = fmaf(A0, wr0.w, fmaf(A1, wr1.w, fmaf(A2, wr2.w, fmaf(A3, wr3.w, acc[r][3]))));
        }
    }
    #pragma unroll
    for (int r = 0; r < 4; ++r)
        #pragma unroll
        for (int j = 0; j < 4; ++j) {
            float v = acc[r][j];
            if (act == 1) v = tanhf(v);
            else if (act == 2) v = sigm(v);
            out[(m0 + r) * D + c0 + j] = v;
        }
}

// ---------------- 5) small GEMM stage 2 with fused epilogues ----------------
__global__ __launch_bounds__(256) void k_small2(
    const float* __restrict__ w0b, const float* __restrict__ a0b,
    const float* __restrict__ v0b, const float* __restrict__ vfirst,
    const float* __restrict__ w2, const float* __restrict__ a2,
    const float* __restrict__ v2, const float* __restrict__ g2)
{
    const int p = blockIdx.y;
    const float* t1; const float* W2; const float* bias; float* out; int D;
    if (p == 0)      { t1 = g_t1w; W2 = w2; bias = w0b; out = g_w; D = 64; }
    else if (p == 1) { t1 = g_t1a; W2 = a2; bias = a0b; out = g_a; D = 64; }
    else if (p == 2) { t1 = g_t1v; W2 = v2; bias = v0b; out = g_v; D = 32; }
    else             { t1 = g_t1g; W2 = g2; bias = 0;   out = g_g; D = 128; }

    __shared__ float ts[8][128];
    const int tid = threadIdx.x;
    const int m0 = blockIdx.x * 8;
    for (int i = tid; i < 8 * D; i += 256)
        ts[i / D][i % D] = t1[(m0 + i / D) * D + (i % D)];
    __syncthreads();

    const int c0 = tid * 4;
    float4 acc0[8], acc1[8];
    #pragma unroll
    for (int r = 0; r < 8; ++r) { acc0[r] = make_float4(0,0,0,0); acc1[r] = make_float4(0,0,0,0); }

    for (int d = 0; d < D; ++d) {
        float4 wA = *(const float4*)(W2 + d * Cc + c0);
        float4 wB = *(const float4*)(W2 + d * Cc + c0 + 1024);
        #pragma unroll
        for (int r = 0; r < 8; ++r) {
            float t = ts[r][d];
            acc0[r].x = fmaf(t, wA.x, acc0[r].x); acc0[r].y = fmaf(t, wA.y, acc0[r].y);
            acc0[r].z = fmaf(t, wA.z, acc0[r].z); acc0[r].w = fmaf(t, wA.w, acc0[r].w);
            acc1[r].x = fmaf(t, wB.x, acc1[r].x); acc1[r].y = fmaf(t, wB.y, acc1[r].y);
            acc1[r].z = fmaf(t, wB.z, acc1[r].z); acc1[r].w = fmaf(t, wB.w, acc1[r].w);
        }
    }

    #pragma unroll
    for (int r = 0; r < 8; ++r) {
        const int row = m0 + r;
        #pragma unroll
        for (int half = 0; half < 2; ++half) {
            float4 acc = half ? acc1[r] : acc0[r];
            int cb = c0 + half * 1024;
            float vals[4] = {acc.x, acc.y, acc.z, acc.w};
            #pragma unroll
            for (int j = 0; j < 4; ++j) {
                int c = cb + j;
                int idx = row * Cc + c;
                float y = vals[j];
                if (p == 0)      out[idx] = 0.60653065971263342f * sigm(bias[c] + y);
                else if (p == 1) out[idx] = sigm(bias[c] + y);
                else if (p == 2) {
                    float s = sigm(bias[c] + y);
                    float vold = out[idx];
                    out[idx] = fmaf(vfirst[idx] - vold, s, vold);
                } else out[idx] = y;
            }
        }
    }
}

// ---------------- 6) per-head: kk normalize, k lerp, b = kk*a ----------------
__global__ void k_kfinal(const float* __restrict__ k_k, const float* __restrict__ k_a) {
    const int gw = blockIdx.x * 8 + (threadIdx.x >> 5);
    const int lane = threadIdx.x & 31;
    const int m = gw >> 5, hh = gw & 31;
    const int cb = hh * 64;
    const int i0 = m * Cc + cb + lane, i1 = i0 + 32;

    float k0 = g_k[i0], k1 = g_k[i1];
    float kk0 = k0 * k_k[cb + lane], kk1 = k1 * k_k[cb + lane + 32];
    float ss = kk0 * kk0 + kk1 * kk1;
    #pragma unroll
    for (int o = 16; o; o >>= 1) ss += __shfl_xor_sync(0xffffffffu, ss, o);
    float inv = 1.0f / fmaxf(sqrtf(ss), 1e-12f);
    kk0 *= inv; kk1 *= inv;
    g_kk[i0] = kk0; g_kk[i1] = kk1;

    float a0v = g_a[i0], a1v = g_a[i1];
    float ka0 = k_a[cb + lane], ka1 = k_a[cb + lane + 32];
    g_k[i0] = k0 + ka0 * (k0 * a0v - k0);
    g_k[i1] = k1 + ka1 * (k1 * a1v - k1);
    g_a[i0] = kk0 * a0v;
    g_a[i1] = kk1 * a1v;
}

// ---------------- 7) WKV7 recurrence ----------------
__device__ __forceinline__ float red16(float x) {
    x += __shfl_xor_sync(0xffffffffu, x, 1);
    x += __shfl_xor_sync(0xffffffffu, x, 2);
    x += __shfl_xor_sync(0xffffffffu, x, 4);
    x += __shfl_xor_sync(0xffffffffu, x, 8);
    return x;
}

__global__ __launch_bounds__(256) void k_wkv(const float* __restrict__ s0) {
    const int tid = threadIdx.x;
    const int vloc = tid >> 4, kg = tid & 15, k0 = kg * 4;
    const int blk = blockIdx.x;
    const int bh = blk >> 2;
    const int v = (blk & 3) * 16 + vloc;
    const int b = bh >> 5, hh = bh & 31;

    float4 S = *(const float4*)(s0 + (bh * 64 + v) * 64 + k0);
    int off = (b * Tt) * Cc + hh * 64;

    const float* pr  = g_r  + k0;
    const float* pk  = g_k  + k0;
    const float* pd  = g_w  + k0;
    const float* pkk = g_kk + k0;
    const float* pb  = g_a  + k0;

    float4 r4  = *(const float4*)(pr  + off);
    float4 k4  = *(const float4*)(pk  + off);
    float4 d4  = *(const float4*)(pd  + off);
    float4 kk4 = *(const float4*)(pkk + off);
    float4 b4  = *(const float4*)(pb  + off);
    float  vt  = g_v[off + v];

    #pragma unroll 1
    for (int t = 0; t < Tt; ++t) {
        float4 rc = r4, kc = k4, dc = d4, kkc = kk4, bc = b4;
        float vc = vt;
        int offn = off + Cc;
        if (t < Tt - 1) {
            r4  = *(const float4*)(pr  + offn);
            k4  = *(const float4*)(pk  + offn);
            d4  = *(const float4*)(pd  + offn);
            kk4 = *(const float4*)(pkk + offn);
            b4  = *(const float4*)(pb  + offn);
            vt  = g_v[offn + v];
        }
        float sap = S.x*kkc.x + S.y*kkc.y + S.z*kkc.z + S.w*kkc.w;
        float sa = -red16(sap);
        S.x = fmaf(S.x, dc.x, fmaf(sa, bc.x, vc * kc.x));
        S.y = fmaf(S.y, dc.y, fmaf(sa, bc.y, vc * kc.y));
        S.z = fmaf(S.z, dc.z, fmaf(sa, bc.z, vc * kc.z));
        S.w = fmaf(S.w, dc.w, fmaf(sa, bc.w, vc * kc.w));
        float op = S.x*rc.x + S.y*rc.y + S.z*rc.z + S.w*rc.w;
        op = red16(op);
        if (kg == 0) g_o[off + v] = op;
        off = offn;
    }
}

// ---------------- 8) groupnorm + bonus + gating -> bf16 split (slot 3) ----------------
__global__ void k_gnorm(const float* __restrict__ rk,
                        const float* __restrict__ gnw, const float* __restrict__ gnb) {
    const int gw = blockIdx.x * 8 + (threadIdx.x >> 5);
    const int lane = threadIdx.x & 31;
    const int m = gw >> 5, hh = gw & 31;
    const int cb = hh * 64;
    const int i0 = m * Cc + cb + lane, i1 = i0 + 32;

    float o0 = g_o[i0], o1 = g_o[i1];
    float s = o0 + o1;
    #pragma unroll
    for (int o = 16; o; o >>= 1) s += __shfl_xor_sync(0xffffffffu, s, o);
    float mean = s * (1.0f / 64.0f);
    float d0 = o0 - mean, d1 = o1 - mean;
    float q = d0 * d0 + d1 * d1;
    #pragma unroll
    for (int o = 16; o; o >>= 1) q += __shfl_xor_sync(0xffffffffu, q, o);
    float inv = rsqrtf(q * (1.0f / 64.0f) + 6.4e-4f);

    float xn0 = d0 * inv * gnw[cb + lane]      + gnb[cb + lane];
    float xn1 = d1 * inv * gnw[cb + lane + 32] + gnb[cb + lane + 32];

    float p = g_r[i0] * g_k[i0] * rk[cb + lane] + g_r[i1] * g_k[i1] * rk[cb + lane + 32];
    #pragma unroll
    for (int o = 16; o; o >>= 1) p += __shfl_xor_sync(0xffffffffu, p, o);

    float x0 = (xn0 + p * g_v[i0]) * g_g[i0];
    float x1 = (xn1 + p * g_v[i1]) * g_g[i1];
    __nv_bfloat16 hi, lo;
    split2(x0, hi, lo); g_Ahi[3][i0] = hi; g_Alo[3][i0] = lo;
    split2(x1, hi, lo); g_Ahi[3][i1] = hi; g_Alo[3][i1] = lo;
}

// ---------------- launch ----------------
extern "C" void kernel_launch(void* const* d_in, const int* in_sizes, int n_in,
                              void* d_out, int out_size) {
    const float* h      = (const float*)d_in[0];
    const float* shift  = (const float*)d_in[1];
    const float* s0     = (const float*)d_in[2];
    const float* vfirst = (const float*)d_in[3];
    const float* x_r = (const float*)d_in[4];
    const float* x_w = (const float*)d_in[5];
    const float* x_k = (const float*)d_in[6];
    const float* x_v = (const float*)d_in[7];
    const float* x_a = (const float*)d_in[8];
    const float* x_g = (const float*)d_in[9];
    const float* w0 = (const float*)d_in[10];
    const float* w1 = (const float*)d_in[11];
    const float* w2 = (const float*)d_in[12];
    const float* a0 = (const float*)d_in[13];
    const float* a1 = (const float*)d_in[14];
    const float* a2 = (const float*)d_in[15];
    const float* v0 = (const float*)d_in[16];
    const float* v1 = (const float*)d_in[17];
    const float* v2 = (const float*)d_in[18];
    const float* g1 = (const float*)d_in[19];
    const float* g2 = (const float*)d_in[20];
    const float* k_k = (const float*)d_in[21];
    const float* k_a = (const float*)d_in[22];
    const float* r_k = (const float*)d_in[23];
    const float* W_r = (const float*)d_in[24];
    const float* W_k = (const float*)d_in[25];
    const float* W_v = (const float*)d_in[26];
    const float* W_o = (const float*)d_in[27];
    const float* gn_w = (const float*)d_in[28];
    const float* gn_b = (const float*)d_in[29];
    float* out = (float*)d_out;

    cudaFuncSetAttribute(k_gemm_tc, cudaFuncAttributeMaxDynamicSharedMemorySize, SMEM_SZ);

    __nv_bfloat16 (*pWhi)[CC]; __nv_bfloat16 (*pWlo)[CC];
    __nv_bfloat16 (*pAhi)[MC]; __nv_bfloat16 (*pAlo)[MC];
    float *pr, *pk, *pv;
    cudaGetSymbolAddress((void**)&pWhi, g_Whi);
    cudaGetSymbolAddress((void**)&pWlo, g_Wlo);
    cudaGetSymbolAddress((void**)&pAhi, g_Ahi);
    cudaGetSymbolAddress((void**)&pAlo, g_Alo);
    cudaGetSymbolAddress((void**)&pr, g_r);
    cudaGetSymbolAddress((void**)&pk, g_k);
    cudaGetSymbolAddress((void**)&pv, g_v);

    k_prep<<<MC / 256, 256>>>(h, shift);
    k_convW<<<dim3(CC / 1024, 4), 256>>>(W_r, W_k, W_v, W_o);
    k_makeA<<<dim3(MC / 1024, 3), 256>>>(h, x_r, x_k, x_v);

    dim3 g16(16, 16);
    k_gemm_tc<<<g16, 256, SMEM_SZ>>>(pAhi[0], pAlo[0], pWhi[0], pWlo[0], pr);
    k_gemm_tc<<<g16, 256, SMEM_SZ>>>(pAhi[1], pAlo[1], pWhi[1], pWlo[1], pk);
    k_gemm_tc<<<g16, 256, SMEM_SZ>>>(pAhi[2], pAlo[2], pWhi[2], pWlo[2], pv);

    k_small1<<<dim3(16, 9), 256>>>(h, x_w, x_a, x_v, x_g, w1, a1, v1, g1);
    k_small2<<<dim3(256, 4), 256>>>(w0, a0, v0, vfirst, w2, a2, v2, g2);
    k_kfinal<<<8192, 256>>>(k_k, k_a);
    k_wkv<<<256, 256>>>(s0);
    k_gnorm<<<8192, 256>>>(r_k, gn_w, gn_b);

    k_gemm_tc<<<g16, 256, SMEM_SZ>>>(pAhi[3], pAlo[3], pWhi[3], pWlo[3], out);
}